// round 7
// baseline (speedup 1.0000x reference)
#include <cuda_runtime.h>
#include <cstdint>

// BaseEncoder: out[b, f, c] = (bitcast<u32>(x[b,f]) >> (31 - c)) & 1  (float),
// c = 0..31.  c==0 is bit 31 = sign bit (== (x<0) channel of the reference);
// c>=1 are bits 30..0 of |x| (abs only clears the sign bit).
//
// Mapping: thread handles one output float4 (channels 4j..4j+3 of one input
// element); 8 consecutive lanes share one input word (broadcast LDG), stores
// are fully coalesced 512 B/warp. Stores use .cs (evict-first streaming):
// the output is write-once, never re-read — keep it out of L2's working set
// so the dirty-line drain to DRAM streams instead of thrashing.

__global__ void __launch_bounds__(256)
base_encoder_kernel(const uint32_t* __restrict__ x,
                    float4* __restrict__ out,
                    int n4)  // n4 = total output floats / 4
{
    const uint32_t ONE = 0x3f800000u;  // bit pattern of 1.0f
    const int stride = gridDim.x * blockDim.x;

    int t = blockIdx.x * blockDim.x + threadIdx.x;

    #pragma unroll 4
    for (; t < n4; t += stride) {
        uint32_t u  = __ldg(&x[t >> 3]);   // input element = (4*t)/32 = t/8
        int      c0 = (t & 7) * 4;         // first bit-channel of this float4

        // Pre-shift once: bit 31 of `base` is channel c0, bit 30 is c0+1, ...
        uint32_t base = u << c0;

        float4 v;
        v.x = __uint_as_float( (base >> 31)        * ONE);
        v.y = __uint_as_float(((base >> 30) & 1u)  * ONE);
        v.z = __uint_as_float(((base >> 29) & 1u)  * ONE);
        v.w = __uint_as_float(((base >> 28) & 1u)  * ONE);

        __stcs(&out[t], v);                // streaming store, evict-first
    }
}

extern "C" void kernel_launch(void* const* d_in, const int* in_sizes, int n_in,
                              void* d_out, int out_size)
{
    const uint32_t* x = (const uint32_t*)d_in[0];
    float4* out = (float4*)d_out;

    int n4 = out_size / 4;                 // 4096*512*32/4 = 16,777,216

    // 4 float4s per thread: 16384 blocks of 256 — enough waves to saturate
    // all 148 SMs while amortizing loop/address overhead.
    int threads = 256;
    int blocks  = (n4 + threads * 4 - 1) / (threads * 4);

    base_encoder_kernel<<<blocks, threads>>>(x, out, n4);
}

// round 8
// speedup vs baseline: 1.2845x; 1.2845x over previous
#include <cuda_runtime.h>
#include <cstdint>

// BaseEncoder: out[b, f, c] = (bitcast<u32>(x[b,f]) >> (31 - c)) & 1  (float).
// c==0 is bit 31 (sign == (x<0) channel); c>=1 are bits 30..0 of |x|.
//
// Latency-hiding structure: each block owns a contiguous chunk of
// 256*ITERS float4s. Each thread front-batches ITERS independent LDGs
// (MLP=ITERS), then computes + stores ITERS float4s. Within each store
// instruction a warp writes 512 contiguous bytes (perfect coalescing).
// Since 256 % 8 == 0, the bit-channel offset (t & 7) is loop-invariant.

constexpr int ITERS   = 8;
constexpr int THREADS = 256;
constexpr int CHUNK   = THREADS * ITERS;   // float4s per block = 2048

__global__ void __launch_bounds__(THREADS)
base_encoder_kernel(const uint32_t* __restrict__ x,
                    float4* __restrict__ out,
                    int n4)
{
    const uint32_t ONE = 0x3f800000u;      // bit pattern of 1.0f

    int t0 = blockIdx.x * CHUNK + threadIdx.x;
    int w0 = t0 >> 3;                      // input word index for iteration 0
    int c0 = (t0 & 7) * 4;                 // loop-invariant bit-channel offset

    if (t0 + (ITERS - 1) * THREADS < n4) {
        // Fast path: all ITERS iterations in bounds.
        uint32_t u[ITERS];
        #pragma unroll
        for (int i = 0; i < ITERS; i++)
            u[i] = __ldg(&x[w0 + i * (THREADS / 8)]);   // 8 lanes share a word

        #pragma unroll
        for (int i = 0; i < ITERS; i++) {
            uint32_t base = u[i] << c0;    // bit 31 of base == channel c0
            float4 v;
            v.x = __uint_as_float( (base >> 31)       * ONE);
            v.y = __uint_as_float(((base >> 30) & 1u) * ONE);
            v.z = __uint_as_float(((base >> 29) & 1u) * ONE);
            v.w = __uint_as_float(((base >> 28) & 1u) * ONE);
            out[t0 + i * THREADS] = v;
        }
    } else {
        // Tail path (unused for the fixed 4096x512x32 shape, kept for safety).
        #pragma unroll
        for (int i = 0; i < ITERS; i++) {
            int t = t0 + i * THREADS;
            if (t < n4) {
                uint32_t base = __ldg(&x[t >> 3]) << c0;
                float4 v;
                v.x = __uint_as_float( (base >> 31)       * ONE);
                v.y = __uint_as_float(((base >> 30) & 1u) * ONE);
                v.z = __uint_as_float(((base >> 29) & 1u) * ONE);
                v.w = __uint_as_float(((base >> 28) & 1u) * ONE);
                out[t] = v;
            }
        }
    }
}

extern "C" void kernel_launch(void* const* d_in, const int* in_sizes, int n_in,
                              void* d_out, int out_size)
{
    const uint32_t* x = (const uint32_t*)d_in[0];
    float4* out = (float4*)d_out;

    int n4 = out_size / 4;                 // 4096*512*32/4 = 16,777,216
    int blocks = (n4 + CHUNK - 1) / CHUNK; // 8192 for the fixed shape

    base_encoder_kernel<<<blocks, THREADS>>>(x, out, n4);
}